// round 1
// baseline (speedup 1.0000x reference)
#include <cuda_runtime.h>
#include <cstdint>

#define N_NODES  50000
#define SEQ      12
#define CH       128
#define BS       4
#define TM       64          // nodes per tile
#define NTHREADS 256
#define PITCH    132         // padded row pitch (floats), 16B-aligned, bank-friendly

typedef unsigned long long ull;

// Packed fp32x2 ops (sm_100+). Full fp32 accuracy at 2x FFMA issue efficiency.
__device__ __forceinline__ ull fma2(ull a, ull b, ull c) {
    ull d; asm("fma.rn.f32x2 %0, %1, %2, %3;" : "=l"(d) : "l"(a), "l"(b), "l"(c)); return d;
}
__device__ __forceinline__ ull mul2(ull a, ull b) {
    ull d; asm("mul.rn.f32x2 %0, %1, %2;" : "=l"(d) : "l"(a), "l"(b)); return d;
}
__device__ __forceinline__ ull dup2(float a) {
    ull d; asm("mov.b64 %0, {%1, %1};" : "=l"(d) : "f"(a)); return d;
}

__global__ void __launch_bounds__(NTHREADS, 2)
gated_spiral_kernel(const float* __restrict__ x,
                    const int*   __restrict__ indices,
                    const float* __restrict__ weight,
                    const float* __restrict__ gate_w,
                    const float* __restrict__ gate_b,
                    float*       __restrict__ out)
{
    extern __shared__ float smem[];
    float* w_s   = smem;                 // [CH][PITCH]  gate_w transposed: w_s[c][d]
    float* xs    = w_s + CH * PITCH;     // [TM][PITCH]  x tile
    float* wt_s  = xs  + TM * PITCH;     // [TM][SEQ]
    int*   idx_s = (int*)(wt_s + TM * SEQ);

    const int tid = threadIdx.x;
    const int tx  = tid & 15;            // channel group (16 groups of 8 ch)
    const int g   = tid >> 4;            // node group   (16 groups of 4 nodes)
    const int f0  = tx << 3;             // first channel of this thread
    const int i0  = g  << 2;             // first node (in tile) of this thread

    // ---- Load gate_w transposed into smem ONCE per (persistent) block ----
    for (int i = tid; i < (CH * CH) / 4; i += NTHREADS) {
        int d = i >> 5;                  // output channel (row of gate_w)
        int c = (i & 31) << 2;           // input channel
        float4 v = reinterpret_cast<const float4*>(gate_w)[i];
        w_s[(c + 0) * PITCH + d] = v.x;
        w_s[(c + 1) * PITCH + d] = v.y;
        w_s[(c + 2) * PITCH + d] = v.z;
        w_s[(c + 3) * PITCH + d] = v.w;
    }
    ull bias[4];
    #pragma unroll
    for (int j = 0; j < 4; j++)
        bias[j] = *reinterpret_cast<const ull*>(gate_b + f0 + 2 * j);

    const int tiles_per_batch = (N_NODES + TM - 1) / TM;   // 782
    const int total_tiles     = BS * tiles_per_batch;      // 3128

    for (int t = blockIdx.x; t < total_tiles; t += gridDim.x) {
        const int b      = t / tiles_per_batch;
        const int v0     = (t - b * tiles_per_batch) * TM;
        const int nvalid = min(TM, N_NODES - v0);
        const float* __restrict__ xb = x + (size_t)b * (size_t)N_NODES * CH;

        __syncthreads();   // protect smem from previous tile's readers

        // ---- Stage x tile (coalesced float4) ----
        for (int i = tid; i < TM * (CH / 4); i += NTHREADS) {
            int r = i >> 5;
            int c = (i & 31) << 2;
            int v = v0 + min(r, nvalid - 1);       // clamp for tail tile
            float4 val = *reinterpret_cast<const float4*>(xb + (size_t)v * CH + c);
            *reinterpret_cast<float4*>(xs + r * PITCH + c) = val;
        }
        // ---- Stage indices / spiral weights ----
        for (int i = tid; i < TM * SEQ; i += NTHREADS) {
            int r = i / SEQ;
            int s = i - r * SEQ;
            if (r < nvalid) {
                idx_s[i] = indices[(v0 + r) * SEQ + s];
                wt_s[i]  = weight [(v0 + r) * SEQ + s];
            } else {
                idx_s[i] = 0;
                wt_s[i]  = 0.f;
            }
        }
        __syncthreads();

        // ---- Phase A: gate GEMM (4 nodes x 8 ch per thread), packed f32x2 ----
        ull acc[4][4];
        #pragma unroll
        for (int ii = 0; ii < 4; ii++)
            #pragma unroll
            for (int j = 0; j < 4; j++) acc[ii][j] = bias[j];

        #pragma unroll 1      // keep body ~1.8 KB for I-cache
        for (int c = 0; c < CH; c += 4) {
            float4 a[4];
            #pragma unroll
            for (int ii = 0; ii < 4; ii++)
                a[ii] = *reinterpret_cast<const float4*>(xs + (i0 + ii) * PITCH + c);
            #pragma unroll
            for (int cc = 0; cc < 4; cc++) {
                const float* wr = w_s + (c + cc) * PITCH + f0;
                ull w0 = *reinterpret_cast<const ull*>(wr);
                ull w1 = *reinterpret_cast<const ull*>(wr + 2);
                ull w2 = *reinterpret_cast<const ull*>(wr + 4);
                ull w3 = *reinterpret_cast<const ull*>(wr + 6);
                #pragma unroll
                for (int ii = 0; ii < 4; ii++) {
                    float av = (cc == 0) ? a[ii].x : (cc == 1) ? a[ii].y
                             : (cc == 2) ? a[ii].z : a[ii].w;
                    ull A = dup2(av);
                    acc[ii][0] = fma2(A, w0, acc[ii][0]);
                    acc[ii][1] = fma2(A, w1, acc[ii][1]);
                    acc[ii][2] = fma2(A, w2, acc[ii][2]);
                    acc[ii][3] = fma2(A, w3, acc[ii][3]);
                }
            }
        }

        // ---- Phase B: spiral gather-reduce, gate-multiply, streaming store ----
        #pragma unroll 1      // one node at a time: 24 outstanding LDG.128, low reg pressure
        for (int ii = 0; ii < 4; ii++) {
            const int node = i0 + ii;
            ull ag0 = 0, ag1 = 0, ag2 = 0, ag3 = 0;
            #pragma unroll
            for (int s = 0; s < SEQ; s++) {
                int   u  = idx_s[node * SEQ + s];
                float wv = wt_s [node * SEQ + s];
                const float* src = xb + (size_t)u * CH + f0;
                ulonglong2 p01 = *reinterpret_cast<const ulonglong2*>(src);
                ulonglong2 p23 = *reinterpret_cast<const ulonglong2*>(src + 4);
                ull W = dup2(wv);
                ag0 = fma2(W, p01.x, ag0);
                ag1 = fma2(W, p01.y, ag1);
                ag2 = fma2(W, p23.x, ag2);
                ag3 = fma2(W, p23.y, ag3);
            }
            if (node < nvalid) {
                ull o0 = mul2(ag0, acc[ii][0]);
                ull o1 = mul2(ag1, acc[ii][1]);
                ull o2 = mul2(ag2, acc[ii][2]);
                ull o3 = mul2(ag3, acc[ii][3]);
                float* op = out + ((size_t)b * N_NODES + (size_t)(v0 + node)) * CH + f0;
                // streaming stores: don't let 102MB of output evict the gather set from L2
                asm volatile("st.global.cs.v2.b64 [%0], {%1,%2};"
                             :: "l"(op),     "l"(o0), "l"(o1) : "memory");
                asm volatile("st.global.cs.v2.b64 [%0], {%1,%2};"
                             :: "l"(op + 4), "l"(o2), "l"(o3) : "memory");
            }
        }
    }
}

extern "C" void kernel_launch(void* const* d_in, const int* in_sizes, int n_in,
                              void* d_out, int out_size)
{
    (void)in_sizes; (void)n_in; (void)out_size;
    const float* x       = (const float*)d_in[0];
    const int*   indices = (const int*)  d_in[1];
    const float* weight  = (const float*)d_in[2];
    const float* gate_w  = (const float*)d_in[3];
    const float* gate_b  = (const float*)d_in[4];
    float*       out     = (float*)d_out;

    const int smem_bytes = (CH * PITCH + TM * PITCH + TM * SEQ) * (int)sizeof(float)
                         + TM * SEQ * (int)sizeof(int);   // ~105 KB

    cudaFuncSetAttribute(gated_spiral_kernel,
                         cudaFuncAttributeMaxDynamicSharedMemorySize, smem_bytes);

    int sm_count = 148;
    cudaDeviceGetAttribute(&sm_count, cudaDevAttrMultiProcessorCount, 0);
    const int grid = 2 * sm_count;   // persistent: 2 blocks/SM

    gated_spiral_kernel<<<grid, NTHREADS, smem_bytes>>>(
        x, indices, weight, gate_w, gate_b, out);
}

// round 2
// speedup vs baseline: 1.1636x; 1.1636x over previous
#include <cuda_runtime.h>
#include <cstdint>

#define N_NODES  50000
#define SEQ      12
#define CH       128
#define BS       4
#define TM       64          // nodes per tile
#define NTHREADS 256
#define PITCH    132         // x-tile row pitch (floats), 16B-aligned

typedef unsigned long long ull;

// Packed fp32x2 ops (sm_100+). Full fp32 accuracy at 2x FFMA issue efficiency.
__device__ __forceinline__ ull fma2(ull a, ull b, ull c) {
    ull d; asm("fma.rn.f32x2 %0, %1, %2, %3;" : "=l"(d) : "l"(a), "l"(b), "l"(c)); return d;
}
__device__ __forceinline__ ull mul2(ull a, ull b) {
    ull d; asm("mul.rn.f32x2 %0, %1, %2;" : "=l"(d) : "l"(a), "l"(b)); return d;
}
__device__ __forceinline__ ull dup2(float a) {
    ull d; asm("mov.b64 %0, {%1, %1};" : "=l"(d) : "f"(a)); return d;
}
__device__ __forceinline__ ull pack2(float lo, float hi) {
    ull d; asm("mov.b64 %0, {%1, %2};" : "=l"(d) : "f"(lo), "f"(hi)); return d;
}

__global__ void __launch_bounds__(NTHREADS, 2)
gated_spiral_kernel(const float* __restrict__ x,
                    const int*   __restrict__ indices,
                    const float* __restrict__ weight,
                    const float* __restrict__ gate_w,
                    const float* __restrict__ gate_b,
                    float*       __restrict__ out)
{
    extern __shared__ float smem[];
    // Pair-interleaved gate_w: ull at index (c*4 + k)*16 + tx holds
    // (gate_w[8tx+2k][c], gate_w[8tx+2k+1][c]).  Lane tx reads stride-8B
    // addresses -> one bank per lane -> conflict-free LDS.64.
    ull*   w2_s  = (ull*)smem;                    // [CH*64] ull = 64 KB
    float* xs    = (float*)(w2_s + CH * 64);      // [TM][PITCH] x tile
    float* wt_s  = xs + TM * PITCH;               // [TM][SEQ]
    int*   idx_s = (int*)(wt_s + TM * SEQ);

    const int tid = threadIdx.x;
    const int tx  = tid & 15;            // channel group (16 groups of 8 ch)
    const int g   = tid >> 4;            // node group   (16 groups of 4 nodes)
    const int f0  = tx << 3;             // first channel of this thread
    const int i0  = g  << 2;             // first node (in tile) of this thread

    // ---- Build pair-interleaved gate_w in smem ONCE per (persistent) block ----
    for (int p = tid; p < (CH * CH) / 2; p += NTHREADS) {
        int c = p >> 6;
        int k = (p >> 4) & 3;
        int t = p & 15;
        int d = (t << 3) + (k << 1);
        float lo = gate_w[d * CH + c];
        float hi = gate_w[(d + 1) * CH + c];
        w2_s[p] = pack2(lo, hi);
    }
    ull bias[4];
    #pragma unroll
    for (int j = 0; j < 4; j++)
        bias[j] = *reinterpret_cast<const ull*>(gate_b + f0 + 2 * j);

    const int tiles_per_batch = (N_NODES + TM - 1) / TM;   // 782
    const int total_tiles     = BS * tiles_per_batch;      // 3128

    for (int t = blockIdx.x; t < total_tiles; t += gridDim.x) {
        const int b      = t / tiles_per_batch;
        const int v0     = (t - b * tiles_per_batch) * TM;
        const int nvalid = min(TM, N_NODES - v0);
        const float* __restrict__ xb = x + (size_t)b * (size_t)N_NODES * CH;

        __syncthreads();   // protect smem from previous tile's readers (also fences w2_s build)

        // ---- Stage x tile (coalesced float4) ----
        for (int i = tid; i < TM * (CH / 4); i += NTHREADS) {
            int r = i >> 5;
            int c = (i & 31) << 2;
            int v = v0 + min(r, nvalid - 1);       // clamp for tail tile
            float4 val = *reinterpret_cast<const float4*>(xb + (size_t)v * CH + c);
            *reinterpret_cast<float4*>(xs + r * PITCH + c) = val;
        }
        // ---- Stage indices / spiral weights ----
        for (int i = tid; i < TM * SEQ; i += NTHREADS) {
            int r = i / SEQ;
            int s = i - r * SEQ;
            if (r < nvalid) {
                idx_s[i] = indices[(v0 + r) * SEQ + s];
                wt_s[i]  = weight [(v0 + r) * SEQ + s];
            } else {
                idx_s[i] = 0;
                wt_s[i]  = 0.f;
            }
        }
        __syncthreads();

        // ---- Phase A: gate GEMM (4 nodes x 8 ch per thread), packed f32x2 ----
        ull acc[4][4];
        #pragma unroll
        for (int ii = 0; ii < 4; ii++)
            #pragma unroll
            for (int j = 0; j < 4; j++) acc[ii][j] = bias[j];

        #pragma unroll 1      // keep body compact for I-cache
        for (int c = 0; c < CH; c += 4) {
            float4 a[4];
            #pragma unroll
            for (int ii = 0; ii < 4; ii++)
                a[ii] = *reinterpret_cast<const float4*>(xs + (i0 + ii) * PITCH + c);
            #pragma unroll
            for (int cc = 0; cc < 4; cc++) {
                const ull* wr = w2_s + ((c + cc) << 6) + tx;
                ull w0 = wr[0];
                ull w1 = wr[16];
                ull w2 = wr[32];
                ull w3 = wr[48];
                #pragma unroll
                for (int ii = 0; ii < 4; ii++) {
                    float av = (cc == 0) ? a[ii].x : (cc == 1) ? a[ii].y
                             : (cc == 2) ? a[ii].z : a[ii].w;
                    ull A = dup2(av);
                    acc[ii][0] = fma2(A, w0, acc[ii][0]);
                    acc[ii][1] = fma2(A, w1, acc[ii][1]);
                    acc[ii][2] = fma2(A, w2, acc[ii][2]);
                    acc[ii][3] = fma2(A, w3, acc[ii][3]);
                }
            }
        }

        // ---- Phase B: spiral gather-reduce, gate-multiply, streaming store ----
        #pragma unroll 1      // one node at a time: 24 outstanding LDG.128, low reg pressure
        for (int ii = 0; ii < 4; ii++) {
            const int node = i0 + ii;
            ull ag0 = 0, ag1 = 0, ag2 = 0, ag3 = 0;
            #pragma unroll
            for (int s = 0; s < SEQ; s++) {
                int   u  = idx_s[node * SEQ + s];
                float wv = wt_s [node * SEQ + s];
                const float* src = xb + (size_t)u * CH + f0;
                ulonglong2 p01 = *reinterpret_cast<const ulonglong2*>(src);
                ulonglong2 p23 = *reinterpret_cast<const ulonglong2*>(src + 4);
                ull W = dup2(wv);
                ag0 = fma2(W, p01.x, ag0);
                ag1 = fma2(W, p01.y, ag1);
                ag2 = fma2(W, p23.x, ag2);
                ag3 = fma2(W, p23.y, ag3);
            }
            if (node < nvalid) {
                ull o0 = mul2(ag0, acc[ii][0]);
                ull o1 = mul2(ag1, acc[ii][1]);
                ull o2 = mul2(ag2, acc[ii][2]);
                ull o3 = mul2(ag3, acc[ii][3]);
                float* op = out + ((size_t)b * N_NODES + (size_t)(v0 + node)) * CH + f0;
                // streaming stores: don't let 102MB of output evict the gather set from L2
                asm volatile("st.global.cs.v2.b64 [%0], {%1,%2};"
                             :: "l"(op),     "l"(o0), "l"(o1) : "memory");
                asm volatile("st.global.cs.v2.b64 [%0], {%1,%2};"
                             :: "l"(op + 4), "l"(o2), "l"(o3) : "memory");
            }
        }
    }
}

extern "C" void kernel_launch(void* const* d_in, const int* in_sizes, int n_in,
                              void* d_out, int out_size)
{
    (void)in_sizes; (void)n_in; (void)out_size;
    const float* x       = (const float*)d_in[0];
    const int*   indices = (const int*)  d_in[1];
    const float* weight  = (const float*)d_in[2];
    const float* gate_w  = (const float*)d_in[3];
    const float* gate_b  = (const float*)d_in[4];
    float*       out     = (float*)d_out;

    const int smem_bytes = CH * 64 * (int)sizeof(ull)                 // w2_s 64 KB
                         + TM * PITCH * (int)sizeof(float)            // xs  ~33.8 KB
                         + TM * SEQ * (int)sizeof(float)              // wt_s
                         + TM * SEQ * (int)sizeof(int);               // idx_s

    cudaFuncSetAttribute(gated_spiral_kernel,
                         cudaFuncAttributeMaxDynamicSharedMemorySize, smem_bytes);

    int sm_count = 148;
    cudaDeviceGetAttribute(&sm_count, cudaDevAttrMultiProcessorCount, 0);
    const int grid = 2 * sm_count;   // persistent: 2 blocks/SM

    gated_spiral_kernel<<<grid, NTHREADS, smem_bytes>>>(
        x, indices, weight, gate_w, gate_b, out);
}

// round 4
// speedup vs baseline: 1.7456x; 1.5002x over previous
#include <cuda_runtime.h>
#include <cuda_bf16.h>
#include <cstdint>

#define N_NODES  50000
#define SEQ      12
#define CH       128
#define BS       4
#define TM       128          // nodes per tile (MMA M)
#define NTHREADS 512
#define AP       136          // bf16 tile pitch (elements): ldmatrix conflict-free
#define GP       132          // gate fp32 pitch (floats): 16B-aligned rows

typedef unsigned long long ull;
typedef unsigned int       uint32;

// ---- smem byte layout ----
#define SM_A0    0                      // A hi bf16 [128][AP]  34816 B
#define SM_A1    34816                  // A lo                 34816 B
#define SM_W0    69632                  // W hi                 34816 B
#define SM_W1    104448                 // W lo                 34816 B
#define SM_GATE  0                      // fp32 [128][GP] overlays A0+A1 (67584 <= 69632)
#define SM_IDX   139264                 // int  [128][12]        6144 B
#define SM_WT    145408                 // f32  [128][12]        6144 B
#define SM_TOTAL 151552

// ---- packed fp32x2 helpers ----
__device__ __forceinline__ ull fma2(ull a, ull b, ull c){ull d;asm("fma.rn.f32x2 %0,%1,%2,%3;":"=l"(d):"l"(a),"l"(b),"l"(c));return d;}
__device__ __forceinline__ ull mul2(ull a, ull b){ull d;asm("mul.rn.f32x2 %0,%1,%2;":"=l"(d):"l"(a),"l"(b));return d;}
__device__ __forceinline__ ull add2(ull a, ull b){ull d;asm("add.rn.f32x2 %0,%1,%2;":"=l"(d):"l"(a),"l"(b));return d;}
__device__ __forceinline__ ull dup2(float a){ull d;asm("mov.b64 %0,{%1,%1};":"=l"(d):"f"(a));return d;}
__device__ __forceinline__ ull pack2(float lo,float hi){ull d;asm("mov.b64 %0,{%1,%2};":"=l"(d):"f"(lo),"f"(hi));return d;}

__device__ __forceinline__ uint32 smem_u32(const void* p){
    uint32 a; asm("{.reg .u64 t; cvta.to.shared.u64 t,%1; cvt.u32.u64 %0,t;}":"=r"(a):"l"(p)); return a;
}

// bf16x2 split of two consecutive floats -> packed hi pair, lo pair
__device__ __forceinline__ void split2(float x, float y, uint32& hi, uint32& lo){
    __nv_bfloat16 bx = __float2bfloat16_rn(x), by = __float2bfloat16_rn(y);
    float rx = x - __bfloat162float(bx), ry = y - __bfloat162float(by);
    __nv_bfloat162 h; h.x = bx; h.y = by;
    __nv_bfloat162 l; l.x = __float2bfloat16_rn(rx); l.y = __float2bfloat16_rn(ry);
    hi = *reinterpret_cast<uint32*>(&h);
    lo = *reinterpret_cast<uint32*>(&l);
}

__device__ __forceinline__ void ldsm_x4(uint32& a0,uint32& a1,uint32& a2,uint32& a3, uint32 addr){
    asm volatile("ldmatrix.sync.aligned.m8n8.x4.shared.b16 {%0,%1,%2,%3},[%4];"
                 : "=r"(a0),"=r"(a1),"=r"(a2),"=r"(a3) : "r"(addr));
}
__device__ __forceinline__ void ldsm_x2(uint32& b0,uint32& b1, uint32 addr){
    asm volatile("ldmatrix.sync.aligned.m8n8.x2.shared.b16 {%0,%1},[%2];"
                 : "=r"(b0),"=r"(b1) : "r"(addr));
}
__device__ __forceinline__ void hmma(float* c, uint32 a0,uint32 a1,uint32 a2,uint32 a3,
                                     uint32 b0,uint32 b1){
    asm volatile("mma.sync.aligned.m16n8k16.row.col.f32.bf16.bf16.f32 "
                 "{%0,%1,%2,%3},{%4,%5,%6,%7},{%8,%9},{%0,%1,%2,%3};"
                 : "+f"(c[0]),"+f"(c[1]),"+f"(c[2]),"+f"(c[3])
                 : "r"(a0),"r"(a1),"r"(a2),"r"(a3),"r"(b0),"r"(b1));
}

__global__ void __launch_bounds__(NTHREADS, 1)
gated_spiral_hmma_kernel(const float* __restrict__ x,
                         const int*   __restrict__ indices,
                         const float* __restrict__ weight,
                         const float* __restrict__ gate_w,
                         const float* __restrict__ gate_b,
                         float*       __restrict__ out)
{
    extern __shared__ char smem[];
    const uint32 sb = smem_u32(smem);
    float* gate_s = (float*)(smem + SM_GATE);
    int*   idx_s  = (int*)  (smem + SM_IDX);
    float* wt_s   = (float*)(smem + SM_WT);

    const int tid  = threadIdx.x;
    const int wid  = tid >> 5;
    const int lane = tid & 31;

    // ---- Stage W (hi/lo bf16 split) once per persistent block ----
    for (int i = tid; i < (CH*CH)/4; i += NTHREADS) {
        int n  = i >> 5;                 // row of gate_w (output channel)
        int k4 = (i & 31) << 2;          // input channel
        float4 v = *reinterpret_cast<const float4*>(gate_w + n*CH + k4);
        uint32 h0,l0,h1,l1;
        split2(v.x, v.y, h0, l0);
        split2(v.z, v.w, h1, l1);
        uint32 o = (uint32)(n*AP + k4) * 2;
        *(uint32*)(smem + SM_W0 + o)     = h0;
        *(uint32*)(smem + SM_W0 + o + 4) = h1;
        *(uint32*)(smem + SM_W1 + o)     = l0;
        *(uint32*)(smem + SM_W1 + o + 4) = l1;
    }
    // per-lane bias for gather phase (lane covers channels 4l..4l+3)
    ull bias0 = *reinterpret_cast<const ull*>(gate_b + lane*4);
    ull bias1 = *reinterpret_cast<const ull*>(gate_b + lane*4 + 2);

    // MMA role: warp computes m-block (wid&7)*16, n-half (wid>>3)*64
    const int mb = wid & 7;
    const int nh = wid >> 3;
    // ldmatrix A address offset (within A tile, bytes): lane pattern for x4
    const uint32 a_loff = (uint32)((mb*16 + (lane & 15))*AP + (lane >> 4)*8) * 2;
    // ldmatrix B address offset for x2 (lanes 0-15 meaningful)
    const uint32 b_loff = (uint32)((nh*64 + (lane & 7))*AP + ((lane >> 3) & 1)*8) * 2;

    const int tiles_per_batch = (N_NODES + TM - 1) / TM;   // 391
    const int total_tiles     = BS * tiles_per_batch;      // 1564

    for (int t = blockIdx.x; t < total_tiles; t += gridDim.x) {
        const int b      = t / tiles_per_batch;
        const int v0     = (t - b * tiles_per_batch) * TM;
        const int nvalid = min(TM, N_NODES - v0);
        const float* __restrict__ xb = x + (size_t)b * (size_t)N_NODES * CH;

        __syncthreads();   // prev tile fully consumed smem (also fences W staging, iter 0)

        // ---- Stage A tile: x -> bf16 hi/lo, [128][AP] ----
        for (int i = tid; i < TM*(CH/4); i += NTHREADS) {
            int r  = i >> 5;
            int k4 = (i & 31) << 2;
            int v  = v0 + min(r, nvalid - 1);
            float4 val = *reinterpret_cast<const float4*>(xb + (size_t)v*CH + k4);
            uint32 h0,l0,h1,l1;
            split2(val.x, val.y, h0, l0);
            split2(val.z, val.w, h1, l1);
            uint32 o = (uint32)(r*AP + k4) * 2;
            *(uint32*)(smem + SM_A0 + o)     = h0;
            *(uint32*)(smem + SM_A0 + o + 4) = h1;
            *(uint32*)(smem + SM_A1 + o)     = l0;
            *(uint32*)(smem + SM_A1 + o + 4) = l1;
        }
        // ---- Stage indices / spiral weights ----
        for (int i = tid; i < TM*SEQ; i += NTHREADS) {
            int r = i / SEQ;
            int s = i - r*SEQ;
            if (r < nvalid) {
                idx_s[i] = indices[(v0 + r)*SEQ + s];
                wt_s[i]  = weight [(v0 + r)*SEQ + s];
            } else { idx_s[i] = 0; wt_s[i] = 0.f; }
        }
        __syncthreads();

        // ---- HMMA: gate = A x W^T, 3 passes (AhWh, AhWl, AlWh) ----
        float acc[8][4];
        #pragma unroll
        for (int nb = 0; nb < 8; nb++)
            #pragma unroll
            for (int j = 0; j < 4; j++) acc[nb][j] = 0.f;

        #pragma unroll
        for (int p = 0; p < 3; p++) {
            const uint32 abase = sb + ((p == 2) ? SM_A1 : SM_A0) + a_loff;
            const uint32 bbase = sb + ((p == 1) ? SM_W1 : SM_W0) + b_loff;
            #pragma unroll
            for (int kb = 0; kb < 8; kb++) {
                uint32 a0,a1,a2,a3;
                ldsm_x4(a0,a1,a2,a3, abase + kb*32);       // 16 bf16 = 32B per k-step
                #pragma unroll
                for (int nb = 0; nb < 8; nb++) {
                    uint32 b0,b1;
                    ldsm_x2(b0,b1, bbase + (uint32)(nb*8*AP)*2 + kb*32);
                    hmma(acc[nb], a0,a1,a2,a3, b0,b1);
                }
            }
        }
        __syncthreads();   // all ldmatrix done before gate overlays A

        // ---- Epilogue: acc -> gate_s fp32 [128][GP] ----
        {
            int r0 = mb*16 + (lane >> 2);
            int c0 = nh*64 + (lane & 3)*2;
            #pragma unroll
            for (int nb = 0; nb < 8; nb++) {
                int c = c0 + nb*8;
                *reinterpret_cast<ull*>(gate_s + r0*GP + c)       = pack2(acc[nb][0], acc[nb][1]);
                *reinterpret_cast<ull*>(gate_s + (r0+8)*GP + c)   = pack2(acc[nb][2], acc[nb][3]);
            }
        }
        __syncthreads();

        // ---- Gather: warp-per-row. Warp w handles nodes w*8..w*8+7; lane = 4 channels ----
        #pragma unroll 1
        for (int nn = 0; nn < 8; nn++) {
            const int node = wid*8 + nn;
            if (node >= nvalid) break;
            ull a0 = 0, a1 = 0;
            #pragma unroll
            for (int s = 0; s < SEQ; s++) {
                int   u  = idx_s[node*SEQ + s];
                float wv = wt_s [node*SEQ + s];
                ulonglong2 p = *reinterpret_cast<const ulonglong2*>(xb + (size_t)u*CH + lane*4);
                ull W = dup2(wv);
                a0 = fma2(W, p.x, a0);
                a1 = fma2(W, p.y, a1);
            }
            ulonglong2 gp = *reinterpret_cast<const ulonglong2*>(gate_s + node*GP + lane*4);
            ull o0 = mul2(a0, add2(gp.x, bias0));
            ull o1 = mul2(a1, add2(gp.y, bias1));
            float* op = out + ((size_t)b*N_NODES + (size_t)(v0 + node))*CH + lane*4;
            asm volatile("st.global.cs.v2.b64 [%0], {%1,%2};" :: "l"(op), "l"(o0), "l"(o1) : "memory");
        }
    }
}

extern "C" void kernel_launch(void* const* d_in, const int* in_sizes, int n_in,
                              void* d_out, int out_size)
{
    (void)in_sizes; (void)n_in; (void)out_size;
    const float* x       = (const float*)d_in[0];
    const int*   indices = (const int*)  d_in[1];
    const float* weight  = (const float*)d_in[2];
    const float* gate_w  = (const float*)d_in[3];
    const float* gate_b  = (const float*)d_in[4];
    float*       out     = (float*)d_out;

    cudaFuncSetAttribute(gated_spiral_hmma_kernel,
                         cudaFuncAttributeMaxDynamicSharedMemorySize, SM_TOTAL);

    int sm_count = 148;
    cudaDeviceGetAttribute(&sm_count, cudaDevAttrMultiProcessorCount, 0);

    gated_spiral_hmma_kernel<<<sm_count, NTHREADS, SM_TOTAL>>>(
        x, indices, weight, gate_w, gate_b, out);
}

// round 5
// speedup vs baseline: 2.0319x; 1.1640x over previous
#include <cuda_runtime.h>
#include <cuda_bf16.h>
#include <cstdint>

#define N_NODES  50000
#define SEQ      12
#define CH       128
#define BS       4
#define TM       128          // nodes per tile (MMA M)
#define NTHREADS 512
#define AP       136          // bf16 tile pitch (elements): ldmatrix conflict-free
#define GP       132          // gate fp32 pitch (floats): 16B-aligned rows

typedef unsigned long long ull;
typedef unsigned int       uint32;

// ---- smem byte layout (no overlays: enables stage/gather overlap) ----
#define SM_A0    0                      // A hi bf16 [128][AP]  34816 B
#define SM_A1    34816                  // A lo                 34816 B
#define SM_W0    69632                  // W hi                 34816 B
#define SM_W1    104448                 // W lo                 34816 B
#define SM_GATE  139264                 // fp32 [128][GP]       67584 B
#define SM_IDX   206848                 // int  [128][12]        6144 B
#define SM_WT    212992                 // f32  [128][12]        6144 B
#define SM_TOTAL 219136

// ---- packed fp32x2 helpers ----
__device__ __forceinline__ ull fma2(ull a, ull b, ull c){ull d;asm("fma.rn.f32x2 %0,%1,%2,%3;":"=l"(d):"l"(a),"l"(b),"l"(c));return d;}
__device__ __forceinline__ ull mul2(ull a, ull b){ull d;asm("mul.rn.f32x2 %0,%1,%2;":"=l"(d):"l"(a),"l"(b));return d;}
__device__ __forceinline__ ull add2(ull a, ull b){ull d;asm("add.rn.f32x2 %0,%1,%2;":"=l"(d):"l"(a),"l"(b));return d;}
__device__ __forceinline__ ull dup2(float a){ull d;asm("mov.b64 %0,{%1,%1};":"=l"(d):"f"(a));return d;}
__device__ __forceinline__ ull pack2(float lo,float hi){ull d;asm("mov.b64 %0,{%1,%2};":"=l"(d):"f"(lo),"f"(hi));return d;}

__device__ __forceinline__ uint32 smem_u32(const void* p){
    uint32 a; asm("{.reg .u64 t; cvta.to.shared.u64 t,%1; cvt.u32.u64 %0,t;}":"=r"(a):"l"(p)); return a;
}

// bf16x2 split of two consecutive floats -> packed hi pair, lo pair
__device__ __forceinline__ void split2(float x, float y, uint32& hi, uint32& lo){
    __nv_bfloat16 bx = __float2bfloat16_rn(x), by = __float2bfloat16_rn(y);
    float rx = x - __bfloat162float(bx), ry = y - __bfloat162float(by);
    __nv_bfloat162 h; h.x = bx; h.y = by;
    __nv_bfloat162 l; l.x = __float2bfloat16_rn(rx); l.y = __float2bfloat16_rn(ry);
    hi = *reinterpret_cast<uint32*>(&h);
    lo = *reinterpret_cast<uint32*>(&l);
}

__device__ __forceinline__ void ldsm_x4(uint32& a0,uint32& a1,uint32& a2,uint32& a3, uint32 addr){
    asm volatile("ldmatrix.sync.aligned.m8n8.x4.shared.b16 {%0,%1,%2,%3},[%4];"
                 : "=r"(a0),"=r"(a1),"=r"(a2),"=r"(a3) : "r"(addr));
}
__device__ __forceinline__ void ldsm_x2(uint32& b0,uint32& b1, uint32 addr){
    asm volatile("ldmatrix.sync.aligned.m8n8.x2.shared.b16 {%0,%1},[%2];"
                 : "=r"(b0),"=r"(b1) : "r"(addr));
}
__device__ __forceinline__ void hmma(float* c, const uint32* a, const uint32* b){
    asm volatile("mma.sync.aligned.m16n8k16.row.col.f32.bf16.bf16.f32 "
                 "{%0,%1,%2,%3},{%4,%5,%6,%7},{%8,%9},{%0,%1,%2,%3};"
                 : "+f"(c[0]),"+f"(c[1]),"+f"(c[2]),"+f"(c[3])
                 : "r"(a[0]),"r"(a[1]),"r"(a[2]),"r"(a[3]),"r"(b[0]),"r"(b[1]));
}

__global__ void __launch_bounds__(NTHREADS, 1)
gated_spiral_hmma_kernel(const float* __restrict__ x,
                         const int*   __restrict__ indices,
                         const float* __restrict__ weight,
                         const float* __restrict__ gate_w,
                         const float* __restrict__ gate_b,
                         float*       __restrict__ out)
{
    extern __shared__ char smem[];
    const uint32 sb = smem_u32(smem);
    float* gate_s = (float*)(smem + SM_GATE);
    int*   idx_s  = (int*)  (smem + SM_IDX);
    float* wt_s   = (float*)(smem + SM_WT);

    const int tid  = threadIdx.x;
    const int wid  = tid >> 5;
    const int lane = tid & 31;

    // ---- Stage W (hi/lo bf16 split) once per persistent block ----
    for (int i = tid; i < (CH*CH)/4; i += NTHREADS) {
        int n  = i >> 5;                 // row of gate_w (output channel)
        int k4 = (i & 31) << 2;          // input channel
        float4 v = *reinterpret_cast<const float4*>(gate_w + n*CH + k4);
        uint32 h0,l0,h1,l1;
        split2(v.x, v.y, h0, l0);
        split2(v.z, v.w, h1, l1);
        uint32 o = (uint32)(n*AP + k4) * 2;
        *(ull*)(smem + SM_W0 + o) = ((ull)h1 << 32) | h0;
        *(ull*)(smem + SM_W1 + o) = ((ull)l1 << 32) | l0;
    }
    // per-lane bias for gather phase (lane covers channels 4l..4l+3)
    const ull bias0 = *reinterpret_cast<const ull*>(gate_b + lane*4);
    const ull bias1 = *reinterpret_cast<const ull*>(gate_b + lane*4 + 2);

    // MMA role: warp (ms, ns) computes rows ms*32..+31, cols ns*32..+31
    const int ms = wid & 3;
    const int ns = wid >> 2;
    // ldmatrix lane-address offsets (bytes within tile)
    const uint32 aoff0 = (uint32)((ms*32      + (lane & 15))*AP + (lane >> 4)*8) * 2;
    const uint32 aoff1 = (uint32)((ms*32 + 16 + (lane & 15))*AP + (lane >> 4)*8) * 2;
    const uint32 boffB = (uint32)((ns*32 + (lane & 7))*AP + ((lane >> 3) & 1)*8) * 2;

    const int tiles_per_batch = (N_NODES + TM - 1) / TM;   // 391
    const int total_tiles     = BS * tiles_per_batch;      // 1564

    // ---- Prologue: stage tile for first t ----
    int t = blockIdx.x;
    if (t < total_tiles) {
        const int b0t = t / tiles_per_batch;
        const int v00 = (t - b0t * tiles_per_batch) * TM;
        const int nv0 = min(TM, N_NODES - v00);
        const float* xb0 = x + (size_t)b0t * (size_t)N_NODES * CH;
        for (int i = tid; i < TM*(CH/4); i += NTHREADS) {
            int r  = i >> 5;
            int k4 = (i & 31) << 2;
            int v  = v00 + min(r, nv0 - 1);
            float4 val = *reinterpret_cast<const float4*>(xb0 + (size_t)v*CH + k4);
            uint32 h0,l0,h1,l1;
            split2(val.x, val.y, h0, l0);
            split2(val.z, val.w, h1, l1);
            uint32 o = (uint32)(r*AP + k4) * 2;
            *(ull*)(smem + SM_A0 + o) = ((ull)h1 << 32) | h0;
            *(ull*)(smem + SM_A1 + o) = ((ull)l1 << 32) | l0;
        }
        #pragma unroll
        for (int k = 0; k < 3; k++) {
            int i = tid + k*NTHREADS;           // < 1536
            int r = i / SEQ, s = i - r*SEQ;
            if (r < nv0) { idx_s[i] = indices[(v00 + r)*SEQ + s]; wt_s[i] = weight[(v00 + r)*SEQ + s]; }
            else         { idx_s[i] = 0;        wt_s[i] = 0.f; }
        }
    }

    for (; t < total_tiles; t += gridDim.x) {
        const int b      = t / tiles_per_batch;
        const int v0     = (t - b * tiles_per_batch) * TM;
        const int nvalid = min(TM, N_NODES - v0);
        const float* __restrict__ xb = x + (size_t)b * (size_t)N_NODES * CH;

        __syncthreads();   // A(t), idx/wt(t) visible; gate_s free (prev gather done)

        // ---- HMMA: gate = A x W^T; per kb load frags once, 3 logical passes ----
        float acc[2][4][4];
        #pragma unroll
        for (int mi = 0; mi < 2; mi++)
            #pragma unroll
            for (int nb = 0; nb < 4; nb++)
                #pragma unroll
                for (int j = 0; j < 4; j++) acc[mi][nb][j] = 0.f;

        #pragma unroll
        for (int kb = 0; kb < 8; kb++) {
            const uint32 ko = kb*32;
            uint32 ah[2][4], al[2][4], bh[4][2], bl[4][2];
            ldsm_x4(ah[0][0],ah[0][1],ah[0][2],ah[0][3], sb + SM_A0 + aoff0 + ko);
            ldsm_x4(ah[1][0],ah[1][1],ah[1][2],ah[1][3], sb + SM_A0 + aoff1 + ko);
            ldsm_x4(al[0][0],al[0][1],al[0][2],al[0][3], sb + SM_A1 + aoff0 + ko);
            ldsm_x4(al[1][0],al[1][1],al[1][2],al[1][3], sb + SM_A1 + aoff1 + ko);
            #pragma unroll
            for (int nb = 0; nb < 4; nb++) {
                const uint32 bo = boffB + (uint32)(nb*8*AP)*2 + ko;
                ldsm_x2(bh[nb][0], bh[nb][1], sb + SM_W0 + bo);
                ldsm_x2(bl[nb][0], bl[nb][1], sb + SM_W1 + bo);
            }
            #pragma unroll
            for (int mi = 0; mi < 2; mi++)
                #pragma unroll
                for (int nb = 0; nb < 4; nb++) {
                    hmma(acc[mi][nb], ah[mi], bh[nb]);   // hi*hi
                    hmma(acc[mi][nb], ah[mi], bl[nb]);   // hi*lo
                    hmma(acc[mi][nb], al[mi], bh[nb]);   // lo*hi
                }
        }

        // ---- Prefetch next tile into registers (latency hidden by gather) ----
        const int  nxt      = t + gridDim.x;
        const bool has_next = (nxt < total_tiles);
        int b2 = 0, v02 = 0, nv2 = TM;
        const float* xb2 = x;
        float4 preA[8];
        int    pidx[3];
        float  pwt[3];
        if (has_next) {
            b2  = nxt / tiles_per_batch;
            v02 = (nxt - b2 * tiles_per_batch) * TM;
            nv2 = min(TM, N_NODES - v02);
            xb2 = x + (size_t)b2 * (size_t)N_NODES * CH;
            #pragma unroll
            for (int k = 0; k < 8; k++) {
                int i  = tid + k*NTHREADS;
                int r  = i >> 5;
                int k4 = (i & 31) << 2;
                int v  = v02 + min(r, nv2 - 1);
                preA[k] = *reinterpret_cast<const float4*>(xb2 + (size_t)v*CH + k4);
            }
            #pragma unroll
            for (int k = 0; k < 3; k++) {
                int i = tid + k*NTHREADS;
                int r = i / SEQ, s = i - r*SEQ;
                if (r < nv2) { pidx[k] = indices[(v02 + r)*SEQ + s]; pwt[k] = weight[(v02 + r)*SEQ + s]; }
                else         { pidx[k] = 0;                          pwt[k] = 0.f; }
            }
        }

        // ---- Epilogue: acc -> gate_s fp32 ----
        #pragma unroll
        for (int mi = 0; mi < 2; mi++) {
            int r0 = ms*32 + mi*16 + (lane >> 2);
            #pragma unroll
            for (int nb = 0; nb < 4; nb++) {
                int c = ns*32 + nb*8 + (lane & 3)*2;
                *reinterpret_cast<ull*>(gate_s + r0*GP + c)     = pack2(acc[mi][nb][0], acc[mi][nb][1]);
                *reinterpret_cast<ull*>(gate_s + (r0+8)*GP + c) = pack2(acc[mi][nb][2], acc[mi][nb][3]);
            }
        }
        __syncthreads();   // gate visible; A-smem free (all ldmatrix retired)

        // ---- Gather: warp-per-row; warp w -> nodes w*8..w*8+7; lane = 4 channels ----
        #pragma unroll 1
        for (int nn = 0; nn < 8; nn++) {
            const int node = wid*8 + nn;
            if (node >= nvalid) break;
            ull a0 = 0, a1 = 0;
            #pragma unroll
            for (int s = 0; s < SEQ; s++) {
                int   u  = idx_s[node*SEQ + s];
                float wv = wt_s [node*SEQ + s];
                ulonglong2 p = *reinterpret_cast<const ulonglong2*>(xb + (size_t)u*CH + lane*4);
                ull W = dup2(wv);
                a0 = fma2(W, p.x, a0);
                a1 = fma2(W, p.y, a1);
            }
            ulonglong2 gp = *reinterpret_cast<const ulonglong2*>(gate_s + node*GP + lane*4);
            ull o0 = mul2(a0, add2(gp.x, bias0));
            ull o1 = mul2(a1, add2(gp.y, bias1));
            float* op = out + ((size_t)b*N_NODES + (size_t)(v0 + node))*CH + lane*4;
            asm volatile("st.global.cs.v2.b64 [%0], {%1,%2};" :: "l"(op), "l"(o0), "l"(o1) : "memory");
        }

        // ---- Store prefetched next tile to A-smem (loads long retired) ----
        if (has_next) {
            #pragma unroll
            for (int k = 0; k < 8; k++) {
                int i  = tid + k*NTHREADS;
                int r  = i >> 5;
                int k4 = (i & 31) << 2;
                uint32 h0,l0,h1,l1;
                split2(preA[k].x, preA[k].y, h0, l0);
                split2(preA[k].z, preA[k].w, h1, l1);
                uint32 o = (uint32)(r*AP + k4) * 2;
                *(ull*)(smem + SM_A0 + o) = ((ull)h1 << 32) | h0;
                *(ull*)(smem + SM_A1 + o) = ((ull)l1 << 32) | l0;
            }
        }
        __syncthreads();   // gather done reading idx/wt(t); safe to overwrite
        if (has_next) {
            #pragma unroll
            for (int k = 0; k < 3; k++) {
                int i = tid + k*NTHREADS;
                idx_s[i] = pidx[k];
                wt_s[i]  = pwt[k];
            }
        }
    }
}

extern "C" void kernel_launch(void* const* d_in, const int* in_sizes, int n_in,
                              void* d_out, int out_size)
{
    (void)in_sizes; (void)n_in; (void)out_size;
    const float* x       = (const float*)d_in[0];
    const int*   indices = (const int*)  d_in[1];
    const float* weight  = (const float*)d_in[2];
    const float* gate_w  = (const float*)d_in[3];
    const float* gate_b  = (const float*)d_in[4];
    float*       out     = (float*)d_out;

    cudaFuncSetAttribute(gated_spiral_hmma_kernel,
                         cudaFuncAttributeMaxDynamicSharedMemorySize, SM_TOTAL);

    int sm_count = 148;
    cudaDeviceGetAttribute(&sm_count, cudaDevAttrMultiProcessorCount, 0);

    gated_spiral_hmma_kernel<<<sm_count, NTHREADS, SM_TOTAL>>>(
        x, indices, weight, gate_w, gate_b, out);
}

// round 6
// speedup vs baseline: 2.1191x; 1.0429x over previous
#include <cuda_runtime.h>
#include <cuda_bf16.h>
#include <cstdint>

#define N_NODES  50000
#define SEQ      12
#define CH       128
#define BS       4
#define TM       64           // nodes per tile
#define NTHREADS 256
#define AP       136          // bf16 A-tile pitch (elements)
#define GP       132          // gate fp32 pitch

typedef unsigned long long ull;
typedef unsigned int       uint32;

// ---- smem layout: A (overlaid by gate) + interleaved idx/wt ----
#define SM_A0    0                      // A hi bf16 [64][AP]   17408 B
#define SM_A1    17408                  // A lo                 17408 B
#define SM_GATE  0                      // fp32 [64][GP] 33792 B, overlays A0+A1
#define SM_IW    34816                  // int2 [64][12]         6144 B
#define SM_TOTAL 41024

// W fragments precomputed in HMMA B-fragment order: [ns][kb][lane][16] uint32
__device__ uint32 g_wfrag[4*8*32*16];   // 64 KB

__device__ __forceinline__ ull fma2(ull a, ull b, ull c){ull d;asm("fma.rn.f32x2 %0,%1,%2,%3;":"=l"(d):"l"(a),"l"(b),"l"(c));return d;}
__device__ __forceinline__ ull mul2(ull a, ull b){ull d;asm("mul.rn.f32x2 %0,%1,%2;":"=l"(d):"l"(a),"l"(b));return d;}
__device__ __forceinline__ ull add2(ull a, ull b){ull d;asm("add.rn.f32x2 %0,%1,%2;":"=l"(d):"l"(a),"l"(b));return d;}
__device__ __forceinline__ ull dup2(float a){ull d;asm("mov.b64 %0,{%1,%1};":"=l"(d):"f"(a));return d;}
__device__ __forceinline__ ull pack2(float lo,float hi){ull d;asm("mov.b64 %0,{%1,%2};":"=l"(d):"f"(lo),"f"(hi));return d;}

__device__ __forceinline__ uint32 smem_u32(const void* p){
    uint32 a; asm("{.reg .u64 t; cvta.to.shared.u64 t,%1; cvt.u32.u64 %0,t;}":"=r"(a):"l"(p)); return a;
}
__device__ __forceinline__ void split2(float x, float y, uint32& hi, uint32& lo){
    __nv_bfloat16 bx = __float2bfloat16_rn(x), by = __float2bfloat16_rn(y);
    float rx = x - __bfloat162float(bx), ry = y - __bfloat162float(by);
    __nv_bfloat162 h; h.x = bx; h.y = by;
    __nv_bfloat162 l; l.x = __float2bfloat16_rn(rx); l.y = __float2bfloat16_rn(ry);
    hi = *reinterpret_cast<uint32*>(&h);
    lo = *reinterpret_cast<uint32*>(&l);
}
__device__ __forceinline__ void ldsm_x4(uint32& a0,uint32& a1,uint32& a2,uint32& a3, uint32 addr){
    asm volatile("ldmatrix.sync.aligned.m8n8.x4.shared.b16 {%0,%1,%2,%3},[%4];"
                 : "=r"(a0),"=r"(a1),"=r"(a2),"=r"(a3) : "r"(addr));
}
__device__ __forceinline__ void hmma(float* c, const uint32* a, const uint32* b){
    asm volatile("mma.sync.aligned.m16n8k16.row.col.f32.bf16.bf16.f32 "
                 "{%0,%1,%2,%3},{%4,%5,%6,%7},{%8,%9},{%0,%1,%2,%3};"
                 : "+f"(c[0]),"+f"(c[1]),"+f"(c[2]),"+f"(c[3])
                 : "r"(a[0]),"r"(a[1]),"r"(a[2]),"r"(a[3]),"r"(b[0]),"r"(b[1]));
}
__device__ __forceinline__ void ldg_cg_v4(const float* p, ull& x, ull& y){
    asm("ld.global.cg.v2.u64 {%0,%1},[%2];" : "=l"(x),"=l"(y) : "l"(p));
}

// ---- build kernel: HMMA B fragments (hi/lo) for gate = A x W^T ----
__global__ void build_wfrag_kernel(const float* __restrict__ gate_w)
{
    int slot = blockIdx.x*blockDim.x + threadIdx.x;   // 0..1023
    if (slot >= 4*8*32) return;
    int lane = slot & 31;
    int kb   = (slot >> 5) & 7;
    int ns   = slot >> 8;
    uint32* dst = g_wfrag + slot*16;
    #pragma unroll
    for (int nb = 0; nb < 4; nb++) {
        int n = ns*32 + nb*8 + (lane >> 2);           // fragment row (n dim)
        #pragma unroll
        for (int i = 0; i < 2; i++) {
            int k0 = kb*16 + i*8 + (lane & 3)*2;      // fragment k pair
            uint32 hi, lo;
            split2(gate_w[n*CH + k0], gate_w[n*CH + k0 + 1], hi, lo);
            dst[nb*4 + 0 + i] = hi;                   // pass 0 (W hi)
            dst[nb*4 + 2 + i] = lo;                   // pass 1 (W lo)
        }
    }
}

__global__ void __launch_bounds__(NTHREADS, 2)
gated_spiral_kernel(const float* __restrict__ x,
                    const int*   __restrict__ indices,
                    const float* __restrict__ weight,
                    const float* __restrict__ gate_b,
                    float*       __restrict__ out)
{
    extern __shared__ char smem[];
    const uint32 sb = smem_u32(smem);
    float* gate_s = (float*)(smem + SM_GATE);
    int2*  iw_s   = (int2*) (smem + SM_IW);

    const int tid  = threadIdx.x;
    const int wid  = tid >> 5;
    const int lane = tid & 31;

    // per-lane bias (lane covers channels 4l..4l+3)
    const ull bias0 = *reinterpret_cast<const ull*>(gate_b + lane*4);
    const ull bias1 = *reinterpret_cast<const ull*>(gate_b + lane*4 + 2);

    // MMA role: 8 warps = 2m x 4n grid; warp tile m32 x n32
    const int ms = wid & 1;
    const int ns = wid >> 1;
    const uint32 aoff0 = (uint32)((ms*32      + (lane & 15))*AP + (lane >> 4)*8) * 2;
    const uint32 aoff1 = (uint32)((ms*32 + 16 + (lane & 15))*AP + (lane >> 4)*8) * 2;

    const int tiles_per_batch = (N_NODES + TM - 1) / TM;   // 782
    const int total_tiles     = BS * tiles_per_batch;      // 3128

    // ---- stage helper (A tile + idx/wt) ----
    auto stage = [&](int tt) {
        const int bb  = tt / tiles_per_batch;
        const int vv0 = (tt - bb * tiles_per_batch) * TM;
        const int nv  = min(TM, N_NODES - vv0);
        const float* xs = x + (size_t)bb * (size_t)N_NODES * CH;
        #pragma unroll
        for (int k = 0; k < 8; k++) {                  // 64*32 float4 / 256 thr
            int i  = tid + k*NTHREADS;
            int r  = i >> 5;
            int k4 = (i & 31) << 2;
            const float* p = xs + (size_t)(vv0 + min(r, nv - 1))*CH + k4;
            ull lo, hi2; ldg_cg_v4(p, lo, hi2);
            float2 v01 = *reinterpret_cast<float2*>(&lo);
            float2 v23 = *reinterpret_cast<float2*>(&hi2);
            uint32 h0,l0,h1,l1;
            split2(v01.x, v01.y, h0, l0);
            split2(v23.x, v23.y, h1, l1);
            uint32 o = (uint32)(r*AP + k4) * 2;
            *(ull*)(smem + SM_A0 + o) = ((ull)h1 << 32) | h0;
            *(ull*)(smem + SM_A1 + o) = ((ull)l1 << 32) | l0;
        }
        #pragma unroll
        for (int k = 0; k < 3; k++) {                  // 64*12 = 768 pairs
            int i = tid + k*NTHREADS;
            int r = i / SEQ, s = i - r*SEQ;
            int2 v;
            if (r < nv) { v.x = indices[(vv0 + r)*SEQ + s];
                          v.y = __float_as_int(weight[(vv0 + r)*SEQ + s]); }
            else        { v.x = 0; v.y = 0; }
            iw_s[i] = v;
        }
    };

    int t = blockIdx.x;
    if (t < total_tiles) stage(t);

    for (; t < total_tiles; t += gridDim.x) {
        const int b      = t / tiles_per_batch;
        const int v0     = (t - b * tiles_per_batch) * TM;
        const int nvalid = min(TM, N_NODES - v0);
        const float* __restrict__ xb = x + (size_t)b * (size_t)N_NODES * CH;

        __syncthreads();   // A(t), iw(t) visible

        // ---- HMMA: per kb load A frags (smem) + W frags (gmem, L1-hot) ----
        float acc[2][4][4];
        #pragma unroll
        for (int mi = 0; mi < 2; mi++)
            #pragma unroll
            for (int nb = 0; nb < 4; nb++)
                #pragma unroll
                for (int j = 0; j < 4; j++) acc[mi][nb][j] = 0.f;

        #pragma unroll
        for (int kb = 0; kb < 8; kb++) {
            const uint32 ko = kb*32;
            uint32 ah[2][4], al[2][4], bf[16];
            ldsm_x4(ah[0][0],ah[0][1],ah[0][2],ah[0][3], sb + SM_A0 + aoff0 + ko);
            ldsm_x4(ah[1][0],ah[1][1],ah[1][2],ah[1][3], sb + SM_A0 + aoff1 + ko);
            ldsm_x4(al[0][0],al[0][1],al[0][2],al[0][3], sb + SM_A1 + aoff0 + ko);
            ldsm_x4(al[1][0],al[1][1],al[1][2],al[1][3], sb + SM_A1 + aoff1 + ko);
            const uint4* wp = reinterpret_cast<const uint4*>(
                g_wfrag + (((ns << 3) + kb)*32 + lane)*16);
            #pragma unroll
            for (int q = 0; q < 4; q++)
                *reinterpret_cast<uint4*>(&bf[q*4]) = wp[q];
            #pragma unroll
            for (int mi = 0; mi < 2; mi++)
                #pragma unroll
                for (int nb = 0; nb < 4; nb++) {
                    hmma(acc[mi][nb], ah[mi], &bf[nb*4]);       // hi*hi
                    hmma(acc[mi][nb], ah[mi], &bf[nb*4 + 2]);   // hi*lo
                    hmma(acc[mi][nb], al[mi], &bf[nb*4]);       // lo*hi
                }
        }
        __syncthreads();   // all ldsm retired before gate overlays A

        // ---- Epilogue: acc -> gate_s fp32 [64][GP] ----
        #pragma unroll
        for (int mi = 0; mi < 2; mi++) {
            int r0 = ms*32 + mi*16 + (lane >> 2);
            #pragma unroll
            for (int nb = 0; nb < 4; nb++) {
                int c = ns*32 + nb*8 + (lane & 3)*2;
                *reinterpret_cast<ull*>(gate_s + r0*GP + c)     = pack2(acc[mi][nb][0], acc[mi][nb][1]);
                *reinterpret_cast<ull*>(gate_s + (r0+8)*GP + c) = pack2(acc[mi][nb][2], acc[mi][nb][3]);
            }
        }
        __syncthreads();   // gate visible

        // ---- Gather: warp-per-row; warp w -> nodes w*8..w*8+7; lane = 4 channels ----
        #pragma unroll 1
        for (int nn = 0; nn < 8; nn++) {
            const int node = wid*8 + nn;
            if (node >= nvalid) break;
            ull a0 = 0, a1 = 0;
            #pragma unroll
            for (int s = 0; s < SEQ; s++) {
                int2 iw = iw_s[node*SEQ + s];
                const float* src = xb + (size_t)(uint32)iw.x*CH + lane*4;
                ull p0, p1; ldg_cg_v4(src, p0, p1);
                ull W = dup2(__int_as_float(iw.y));
                a0 = fma2(W, p0, a0);
                a1 = fma2(W, p1, a1);
            }
            ulonglong2 gp = *reinterpret_cast<const ulonglong2*>(gate_s + node*GP + lane*4);
            ull o0 = mul2(a0, add2(gp.x, bias0));
            ull o1 = mul2(a1, add2(gp.y, bias1));
            float* op = out + ((size_t)b*N_NODES + (size_t)(v0 + node))*CH + lane*4;
            asm volatile("st.global.cs.v2.b64 [%0], {%1,%2};" :: "l"(op), "l"(o0), "l"(o1) : "memory");
        }

        __syncthreads();   // gather done reading gate + iw

        // ---- Stage next tile ----
        const int nxt = t + gridDim.x;
        if (nxt < total_tiles) stage(nxt);
    }
}

extern "C" void kernel_launch(void* const* d_in, const int* in_sizes, int n_in,
                              void* d_out, int out_size)
{
    (void)in_sizes; (void)n_in; (void)out_size;
    const float* x       = (const float*)d_in[0];
    const int*   indices = (const int*)  d_in[1];
    const float* weight  = (const float*)d_in[2];
    const float* gate_w  = (const float*)d_in[3];
    const float* gate_b  = (const float*)d_in[4];
    float*       out     = (float*)d_out;

    build_wfrag_kernel<<<4, 256>>>(gate_w);

    cudaFuncSetAttribute(gated_spiral_kernel,
                         cudaFuncAttributeMaxDynamicSharedMemorySize, SM_TOTAL);

    int sm_count = 148;
    cudaDeviceGetAttribute(&sm_count, cudaDevAttrMultiProcessorCount, 0);

    gated_spiral_kernel<<<2*sm_count, NTHREADS, SM_TOTAL>>>(
        x, indices, weight, gate_b, out);
}

// round 7
// speedup vs baseline: 2.6327x; 1.2423x over previous
#include <cuda_runtime.h>
#include <cuda_bf16.h>
#include <cstdint>

#define N_NODES  50000
#define SEQ      12
#define CH       128
#define BS       4
#define TM       64           // nodes per tile
#define NTHREADS 256
#define AP       136          // bf16 A-tile pitch (elements)
#define GP       132          // gate fp32 pitch

typedef unsigned long long ull;
typedef unsigned int       uint32;

// ---- smem layout: A (overlaid by gate) + interleaved idx/wt ----
#define SM_A0    0                      // A hi bf16 [64][AP]   17408 B
#define SM_A1    17408                  // A lo                 17408 B
#define SM_GATE  0                      // fp32 [64][GP] 33792 B, overlays A0+A1
#define SM_IW    34816                  // int2 [64][12]         6144 B
#define SM_TOTAL 41024

// W fragments, coalesced: uint4 at [((ns*8+kb)*4+q)*32 + lane]
// lane-stride 16B -> every LDG.128 covers one contiguous 512B line-pair (4 wf).
__device__ uint4 g_wfrag[4*8*4*32];     // 64 KB

__device__ __forceinline__ ull fma2(ull a, ull b, ull c){ull d;asm("fma.rn.f32x2 %0,%1,%2,%3;":"=l"(d):"l"(a),"l"(b),"l"(c));return d;}
__device__ __forceinline__ ull mul2(ull a, ull b){ull d;asm("mul.rn.f32x2 %0,%1,%2;":"=l"(d):"l"(a),"l"(b));return d;}
__device__ __forceinline__ ull add2(ull a, ull b){ull d;asm("add.rn.f32x2 %0,%1,%2;":"=l"(d):"l"(a),"l"(b));return d;}
__device__ __forceinline__ ull dup2(float a){ull d;asm("mov.b64 %0,{%1,%1};":"=l"(d):"f"(a));return d;}
__device__ __forceinline__ ull pack2(float lo,float hi){ull d;asm("mov.b64 %0,{%1,%2};":"=l"(d):"f"(lo),"f"(hi));return d;}

__device__ __forceinline__ uint32 smem_u32(const void* p){
    uint32 a; asm("{.reg .u64 t; cvta.to.shared.u64 t,%1; cvt.u32.u64 %0,t;}":"=r"(a):"l"(p)); return a;
}
__device__ __forceinline__ void split2(float x, float y, uint32& hi, uint32& lo){
    __nv_bfloat16 bx = __float2bfloat16_rn(x), by = __float2bfloat16_rn(y);
    float rx = x - __bfloat162float(bx), ry = y - __bfloat162float(by);
    __nv_bfloat162 h; h.x = bx; h.y = by;
    __nv_bfloat162 l; l.x = __float2bfloat16_rn(rx); l.y = __float2bfloat16_rn(ry);
    hi = *reinterpret_cast<uint32*>(&h);
    lo = *reinterpret_cast<uint32*>(&l);
}
__device__ __forceinline__ void ldsm_x4(uint32& a0,uint32& a1,uint32& a2,uint32& a3, uint32 addr){
    asm volatile("ldmatrix.sync.aligned.m8n8.x4.shared.b16 {%0,%1,%2,%3},[%4];"
                 : "=r"(a0),"=r"(a1),"=r"(a2),"=r"(a3) : "r"(addr));
}
__device__ __forceinline__ void hmma(float* c, const uint32* a, const uint32* b){
    asm volatile("mma.sync.aligned.m16n8k16.row.col.f32.bf16.bf16.f32 "
                 "{%0,%1,%2,%3},{%4,%5,%6,%7},{%8,%9},{%0,%1,%2,%3};"
                 : "+f"(c[0]),"+f"(c[1]),"+f"(c[2]),"+f"(c[3])
                 : "r"(a[0]),"r"(a[1]),"r"(a[2]),"r"(a[3]),"r"(b[0]),"r"(b[1]));
}
__device__ __forceinline__ void ldg_cg_v4(const float* p, ull& x, ull& y){
    asm("ld.global.cg.v2.u64 {%0,%1},[%2];" : "=l"(x),"=l"(y) : "l"(p));
}

// ---- build kernel: HMMA B fragments for gate = A x W^T, coalesced layout ----
__global__ void build_wfrag_kernel(const float* __restrict__ gate_w)
{
    int slot = blockIdx.x*blockDim.x + threadIdx.x;   // 0..1023
    if (slot >= 4*8*32) return;
    int lane = slot & 31;
    int kb   = (slot >> 5) & 7;
    int ns   = slot >> 8;
    #pragma unroll
    for (int nb = 0; nb < 4; nb++) {
        int n = ns*32 + nb*8 + (lane >> 2);           // fragment row (n dim)
        uint32 h[2], l[2];
        #pragma unroll
        for (int i = 0; i < 2; i++) {
            int k0 = kb*16 + i*8 + (lane & 3)*2;      // fragment k pair
            split2(gate_w[n*CH + k0], gate_w[n*CH + k0 + 1], h[i], l[i]);
        }
        uint4 v; v.x = h[0]; v.y = h[1]; v.z = l[0]; v.w = l[1];
        g_wfrag[(((ns << 3) + kb)*4 + nb)*32 + lane] = v;
    }
}

__global__ void __launch_bounds__(NTHREADS, 2)
gated_spiral_kernel(const float* __restrict__ x,
                    const int*   __restrict__ indices,
                    const float* __restrict__ weight,
                    const float* __restrict__ gate_b,
                    float*       __restrict__ out)
{
    extern __shared__ char smem[];
    const uint32 sb = smem_u32(smem);
    float* gate_s = (float*)(smem + SM_GATE);
    int2*  iw_s   = (int2*) (smem + SM_IW);

    const int tid  = threadIdx.x;
    const int wid  = tid >> 5;
    const int lane = tid & 31;

    // per-lane bias (lane covers channels 4l..4l+3)
    const ull bias0 = *reinterpret_cast<const ull*>(gate_b + lane*4);
    const ull bias1 = *reinterpret_cast<const ull*>(gate_b + lane*4 + 2);

    // MMA role: 8 warps = 2m x 4n grid; warp tile m32 x n32
    const int ms = wid & 1;
    const int ns = wid >> 1;
    const uint32 aoff0 = (uint32)((ms*32      + (lane & 15))*AP + (lane >> 4)*8) * 2;
    const uint32 aoff1 = (uint32)((ms*32 + 16 + (lane & 15))*AP + (lane >> 4)*8) * 2;

    const int tiles_per_batch = (N_NODES + TM - 1) / TM;   // 782
    const int total_tiles     = BS * tiles_per_batch;      // 3128

    // ---- stage helper (A tile + idx/wt) ----
    auto stage = [&](int tt) {
        const int bb  = tt / tiles_per_batch;
        const int vv0 = (tt - bb * tiles_per_batch) * TM;
        const int nv  = min(TM, N_NODES - vv0);
        const float* xs = x + (size_t)bb * (size_t)N_NODES * CH;
        #pragma unroll
        for (int k = 0; k < 8; k++) {                  // 64*32 float4 / 256 thr
            int i  = tid + k*NTHREADS;
            int r  = i >> 5;
            int k4 = (i & 31) << 2;
            const float* p = xs + (size_t)(vv0 + min(r, nv - 1))*CH + k4;
            ull lo, hi2; ldg_cg_v4(p, lo, hi2);
            float2 v01 = *reinterpret_cast<float2*>(&lo);
            float2 v23 = *reinterpret_cast<float2*>(&hi2);
            uint32 h0,l0,h1,l1;
            split2(v01.x, v01.y, h0, l0);
            split2(v23.x, v23.y, h1, l1);
            uint32 o = (uint32)(r*AP + k4) * 2;
            *(ull*)(smem + SM_A0 + o) = ((ull)h1 << 32) | h0;
            *(ull*)(smem + SM_A1 + o) = ((ull)l1 << 32) | l0;
        }
        #pragma unroll
        for (int k = 0; k < 3; k++) {                  // 64*12 = 768 pairs
            int i = tid + k*NTHREADS;
            int r = i / SEQ, s = i - r*SEQ;
            int2 v;
            if (r < nv) { v.x = indices[(vv0 + r)*SEQ + s];
                          v.y = __float_as_int(weight[(vv0 + r)*SEQ + s]); }
            else        { v.x = 0; v.y = 0; }
            iw_s[i] = v;
        }
    };

    int t = blockIdx.x;
    if (t < total_tiles) stage(t);

    for (; t < total_tiles; t += gridDim.x) {
        const int b      = t / tiles_per_batch;
        const int v0     = (t - b * tiles_per_batch) * TM;
        const int nvalid = min(TM, N_NODES - v0);
        const float* __restrict__ xb = x + (size_t)b * (size_t)N_NODES * CH;

        __syncthreads();   // A(t), iw(t) visible

        // ---- HMMA: per kb load A frags (smem) + W frags (gmem, L1-hot, coalesced) ----
        float acc[2][4][4];
        #pragma unroll
        for (int mi = 0; mi < 2; mi++)
            #pragma unroll
            for (int nb = 0; nb < 4; nb++)
                #pragma unroll
                for (int j = 0; j < 4; j++) acc[mi][nb][j] = 0.f;

        #pragma unroll
        for (int kb = 0; kb < 8; kb++) {
            const uint32 ko = kb*32;
            uint32 ah[2][4], al[2][4], bf[16];
            ldsm_x4(ah[0][0],ah[0][1],ah[0][2],ah[0][3], sb + SM_A0 + aoff0 + ko);
            ldsm_x4(ah[1][0],ah[1][1],ah[1][2],ah[1][3], sb + SM_A0 + aoff1 + ko);
            ldsm_x4(al[0][0],al[0][1],al[0][2],al[0][3], sb + SM_A1 + aoff0 + ko);
            ldsm_x4(al[1][0],al[1][1],al[1][2],al[1][3], sb + SM_A1 + aoff1 + ko);
            const uint4* wp = g_wfrag + (((ns << 3) + kb) << 2)*32 + lane;
            #pragma unroll
            for (int q = 0; q < 4; q++)
                *reinterpret_cast<uint4*>(&bf[q*4]) = wp[q*32];
            #pragma unroll
            for (int mi = 0; mi < 2; mi++)
                #pragma unroll
                for (int nb = 0; nb < 4; nb++) {
                    hmma(acc[mi][nb], ah[mi], &bf[nb*4]);       // hi*hi
                    hmma(acc[mi][nb], ah[mi], &bf[nb*4 + 2]);   // hi*lo
                    hmma(acc[mi][nb], al[mi], &bf[nb*4]);       // lo*hi
                }
        }
        __syncthreads();   // all ldsm retired before gate overlays A

        // ---- Epilogue: acc -> gate_s fp32 [64][GP] ----
        #pragma unroll
        for (int mi = 0; mi < 2; mi++) {
            int r0 = ms*32 + mi*16 + (lane >> 2);
            #pragma unroll
            for (int nb = 0; nb < 4; nb++) {
                int c = ns*32 + nb*8 + (lane & 3)*2;
                *reinterpret_cast<ull*>(gate_s + r0*GP + c)     = pack2(acc[mi][nb][0], acc[mi][nb][1]);
                *reinterpret_cast<ull*>(gate_s + (r0+8)*GP + c) = pack2(acc[mi][nb][2], acc[mi][nb][3]);
            }
        }
        __syncthreads();   // gate visible

        // ---- Gather: warp-per-row; warp w -> nodes w*8..w*8+7; lane = 4 channels ----
        #pragma unroll 1
        for (int nn = 0; nn < 8; nn++) {
            const int node = wid*8 + nn;
            if (node >= nvalid) break;
            ull a0 = 0, a1 = 0;
            #pragma unroll
            for (int s = 0; s < SEQ; s++) {
                int2 iw = iw_s[node*SEQ + s];
                const float* src = xb + (size_t)(uint32)iw.x*CH + lane*4;
                ull p0, p1; ldg_cg_v4(src, p0, p1);
                ull W = dup2(__int_as_float(iw.y));
                a0 = fma2(W, p0, a0);
                a1 = fma2(W, p1, a1);
            }
            ulonglong2 gp = *reinterpret_cast<const ulonglong2*>(gate_s + node*GP + lane*4);
            ull o0 = mul2(a0, add2(gp.x, bias0));
            ull o1 = mul2(a1, add2(gp.y, bias1));
            float* op = out + ((size_t)b*N_NODES + (size_t)(v0 + node))*CH + lane*4;
            asm volatile("st.global.cs.v2.b64 [%0], {%1,%2};" :: "l"(op), "l"(o0), "l"(o1) : "memory");
        }

        __syncthreads();   // gather done reading gate + iw

        // ---- Stage next tile ----
        const int nxt = t + gridDim.x;
        if (nxt < total_tiles) stage(nxt);
    }
}

extern "C" void kernel_launch(void* const* d_in, const int* in_sizes, int n_in,
                              void* d_out, int out_size)
{
    (void)in_sizes; (void)n_in; (void)out_size;
    const float* x       = (const float*)d_in[0];
    const int*   indices = (const int*)  d_in[1];
    const float* weight  = (const float*)d_in[2];
    const float* gate_w  = (const float*)d_in[3];
    const float* gate_b  = (const float*)d_in[4];
    float*       out     = (float*)d_out;

    build_wfrag_kernel<<<4, 256>>>(gate_w);

    cudaFuncSetAttribute(gated_spiral_kernel,
                         cudaFuncAttributeMaxDynamicSharedMemorySize, SM_TOTAL);

    int sm_count = 148;
    cudaDeviceGetAttribute(&sm_count, cudaDevAttrMultiProcessorCount, 0);

    gated_spiral_kernel<<<2*sm_count, NTHREADS, SM_TOTAL>>>(
        x, indices, weight, gate_b, out);
}